// round 7
// baseline (speedup 1.0000x reference)
#include <cuda_runtime.h>
#include <math.h>

// Problem constants
#define Nn 128
#define Cc 64
#define Tt 128
#define Vv 25
#define Rr 8
#define Hh 12

// Scratch (device globals; no allocation allowed)
__device__ float g_xm[Nn * Cc * Vv];          // mean over T      (0.8 MB)
__device__ float g_Aeff[Nn * Cc * Vv * Vv];   // effective adjacency incl. SE scale (20.5 MB)

// ================= Kernel 1: xm[n,c,v] = mean_t x[n,c,t,v] =================
// One block per (n,c), 200 threads. Thread j loads float4s at q = j, j+200,
// j+400, j+600 (stride 800 floats == 0 mod 25 -> each component keeps a FIXED
// v). Register accumulation, then a conflict-free stride-25 shared reduction.
__global__ void __launch_bounds__(200) k1_meanT(const float* __restrict__ x) {
    const int b = blockIdx.x;                 // n*C + c
    const int j = threadIdx.x;                // 0..199
    const float4* xp4 = reinterpret_cast<const float4*>(x + (size_t)b * (Tt * Vv));

    float4 a0 = xp4[j];
    float4 a1 = xp4[j + 200];
    float4 a2 = xp4[j + 400];
    float4 a3 = xp4[j + 600];

    __shared__ float red[800];
    red[4 * j + 0] = a0.x + a1.x + a2.x + a3.x;
    red[4 * j + 1] = a0.y + a1.y + a2.y + a3.y;
    red[4 * j + 2] = a0.z + a1.z + a2.z + a3.z;
    red[4 * j + 3] = a0.w + a1.w + a2.w + a3.w;
    __syncthreads();

    if (j < Vv) {
        float tot = 0.f;
        #pragma unroll
        for (int p = 0; p < 32; p++) tot += red[j + Vv * p];
        g_xm[b * Vv + j] = tot * (1.0f / Tt);
    }
}

// ============ Kernel 2: per-n relation matrix + SE attention ============
// Grid (128, 4): each block recomputes the tiny SE / x1 / x2 / rel stage and
// writes 16 of the 64 output channels of
//   Aeff[n,c,u,v] = (sum_r w4[c,r]*tanh(x1[r,u]-x2[r,v]) + b4[c] + A[u,v]) * a[n,v]
__global__ void k2_adj(const float* __restrict__ A,
                       const float* __restrict__ w1, const float* __restrict__ b1,
                       const float* __restrict__ w2, const float* __restrict__ b2,
                       const float* __restrict__ w4, const float* __restrict__ b4,
                       const float* __restrict__ sw1, const float* __restrict__ sb1,
                       const float* __restrict__ sw2, const float* __restrict__ sb2) {
    const int n = blockIdx.x;
    const int cblk = blockIdx.y;              // channels [cblk*16, cblk*16+16)
    const int tid = threadIdx.x;
    const int NT = 256;

    __shared__ float xm_sh[Cc * Vv];
    __shared__ float w1s[Rr * Cc], w2s[Rr * Cc], w4s[Cc * Rr];
    __shared__ float sw1s[Hh * Vv], sw2s[Vv * Hh];
    __shared__ float A_s[Vv * Vv];
    __shared__ float b1s[Rr], b2s[Rr], b4s[Cc], sb1s[Hh], sb2s[Vv];
    __shared__ float s_sh[Vv], h_sh[Hh], a_sh[Vv];
    __shared__ float x1_sh[Rr * Vv], x2_sh[Rr * Vv];
    __shared__ float rel_sh[Rr * Vv * Vv];

    for (int i = tid; i < Cc * Vv; i += NT) xm_sh[i] = g_xm[n * Cc * Vv + i];
    for (int i = tid; i < Rr * Cc; i += NT) { w1s[i] = w1[i]; w2s[i] = w2[i]; w4s[i] = w4[i]; }
    for (int i = tid; i < Hh * Vv; i += NT) { sw1s[i] = sw1[i]; sw2s[i] = sw2[i]; }
    for (int i = tid; i < Vv * Vv; i += NT) A_s[i] = A[i];
    if (tid < Rr) { b1s[tid] = b1[tid]; b2s[tid] = b2[tid]; }
    if (tid < Cc) b4s[tid] = b4[tid];
    if (tid < Hh) sb1s[tid] = sb1[tid];
    if (tid < Vv) sb2s[tid] = sb2[tid];
    __syncthreads();

    if (tid < Vv) {
        float acc = 0.f;
        for (int c = 0; c < Cc; c++) acc += xm_sh[c * Vv + tid];
        s_sh[tid] = acc * (1.0f / Cc);
    }
    __syncthreads();
    if (tid < Hh) {
        float acc = sb1s[tid];
        for (int v = 0; v < Vv; v++) acc += sw1s[tid * Vv + v] * s_sh[v];
        h_sh[tid] = fmaxf(acc, 0.f);
    }
    __syncthreads();
    if (tid < Vv) {
        float acc = sb2s[tid];
        for (int q = 0; q < Hh; q++) acc += sw2s[tid * Hh + q] * h_sh[q];
        a_sh[tid] = 1.0f / (1.0f + expf(-acc));
    }

    if (tid < Rr * Vv) {
        int r = tid / Vv, v = tid % Vv;
        float acc1 = b1s[r], acc2 = b2s[r];
        for (int c = 0; c < Cc; c++) {
            float xm = xm_sh[c * Vv + v];
            acc1 += w1s[r * Cc + c] * xm;
            acc2 += w2s[r * Cc + c] * xm;
        }
        x1_sh[tid] = acc1;
        x2_sh[tid] = acc2;
    }
    __syncthreads();

    for (int i = tid; i < Rr * Vv * Vv; i += NT) {
        int r = i / (Vv * Vv), rem = i % (Vv * Vv);
        int u = rem / Vv, v = rem % Vv;
        rel_sh[i] = tanhf(x1_sh[r * Vv + u] - x2_sh[r * Vv + v]);
    }
    __syncthreads();

    const int c0 = cblk * 16;
    float* outp = g_Aeff + ((size_t)n * Cc + c0) * (Vv * Vv);
    for (int i = tid; i < 16 * Vv * Vv; i += NT) {
        int c = c0 + i / (Vv * Vv), rem = i % (Vv * Vv);
        int v = rem % Vv;
        float acc = b4s[c] + A_s[rem];
        #pragma unroll
        for (int r = 0; r < Rr; r++) acc += w4s[c * Rr + r] * rel_sh[r * Vv * Vv + rem];
        outp[i] = acc * a_sh[v];
    }
}

// ============ Kernel 3 v3: out[t,u] = sum_v Aeff[u,v] * x[t,v] per (n,c) ============
// 64 threads/block, each thread computes TWO t-rows (t, t+64). This halves
// the dominant L1 cost (per-u weight LDS.128 broadcasts amortize over 64
// outputs/warp instead of 32). Weights padded to 28-float rows for clean
// LDS.128. Streaming stores for out (never re-read).
__global__ void __launch_bounds__(64) k3_gemm(const float* __restrict__ x,
                                              float* __restrict__ out) {
    __shared__ float xs[Tt * Vv];                      // 12.8 KB; reused as out staging
    __shared__ __align__(16) float Ws[Vv * 28];        // padded rows: 112 B each

    const int b = blockIdx.x;           // n*C + c
    const int tid = threadIdx.x;        // 0..63

    // Load x tile (800 float4, coalesced)
    const float4* xp4 = reinterpret_cast<const float4*>(x + (size_t)b * (Tt * Vv));
    float4* xs4 = reinterpret_cast<float4*>(xs);
    #pragma unroll
    for (int i = tid; i < (Tt * Vv) / 4; i += 64) xs4[i] = xp4[i];

    // Load Aeff row-padded (pad cols zeroed)
    const float* ae = g_Aeff + (size_t)b * (Vv * Vv);
    for (int i = tid; i < Vv * 28; i += 64) {
        int u = i / 28, v = i % 28;
        Ws[i] = (v < Vv) ? ae[u * Vv + v] : 0.f;
    }
    __syncthreads();

    // Two x rows in registers (lane stride 25 ⊥ 32: conflict-free)
    const int t0 = tid, t1 = tid + 64;
    float xa[Vv], xb[Vv];
    #pragma unroll
    for (int v = 0; v < Vv; v++) {
        xa[v] = xs[t0 * Vv + v];
        xb[v] = xs[t1 * Vv + v];
    }
    __syncthreads();   // xs now free for output staging

    #pragma unroll 1
    for (int u = 0; u < Vv; u++) {
        const float4* wr = reinterpret_cast<const float4*>(Ws + u * 28);
        float4 w0 = wr[0], w1 = wr[1], w2 = wr[2], w3 = wr[3];
        float4 w4 = wr[4], w5 = wr[5], w6 = wr[6];
        float a0, a1, b0, b1;
        a0  = w0.x * xa[0];   b0  = w0.x * xb[0];
        a1  = w0.y * xa[1];   b1  = w0.y * xb[1];
        a0 += w0.z * xa[2];   b0 += w0.z * xb[2];
        a1 += w0.w * xa[3];   b1 += w0.w * xb[3];
        a0 += w1.x * xa[4];   b0 += w1.x * xb[4];
        a1 += w1.y * xa[5];   b1 += w1.y * xb[5];
        a0 += w1.z * xa[6];   b0 += w1.z * xb[6];
        a1 += w1.w * xa[7];   b1 += w1.w * xb[7];
        a0 += w2.x * xa[8];   b0 += w2.x * xb[8];
        a1 += w2.y * xa[9];   b1 += w2.y * xb[9];
        a0 += w2.z * xa[10];  b0 += w2.z * xb[10];
        a1 += w2.w * xa[11];  b1 += w2.w * xb[11];
        a0 += w3.x * xa[12];  b0 += w3.x * xb[12];
        a1 += w3.y * xa[13];  b1 += w3.y * xb[13];
        a0 += w3.z * xa[14];  b0 += w3.z * xb[14];
        a1 += w3.w * xa[15];  b1 += w3.w * xb[15];
        a0 += w4.x * xa[16];  b0 += w4.x * xb[16];
        a1 += w4.y * xa[17];  b1 += w4.y * xb[17];
        a0 += w4.z * xa[18];  b0 += w4.z * xb[18];
        a1 += w4.w * xa[19];  b1 += w4.w * xb[19];
        a0 += w5.x * xa[20];  b0 += w5.x * xb[20];
        a1 += w5.y * xa[21];  b1 += w5.y * xb[21];
        a0 += w5.z * xa[22];  b0 += w5.z * xb[22];
        a1 += w5.w * xa[23];  b1 += w5.w * xb[23];
        a0 += w6.x * xa[24];  b0 += w6.x * xb[24];
        xs[t0 * Vv + u] = a0 + a1;
        xs[t1 * Vv + u] = b0 + b1;
    }
    __syncthreads();

    float4* op4 = reinterpret_cast<float4*>(out + (size_t)b * (Tt * Vv));
    #pragma unroll
    for (int i = tid; i < (Tt * Vv) / 4; i += 64) __stcs(op4 + i, xs4[i]);
}

extern "C" void kernel_launch(void* const* d_in, const int* in_sizes, int n_in,
                              void* d_out, int out_size) {
    const float* x   = (const float*)d_in[0];
    const float* A   = (const float*)d_in[1];
    const float* w1  = (const float*)d_in[2];
    const float* b1  = (const float*)d_in[3];
    const float* w2  = (const float*)d_in[4];
    const float* b2  = (const float*)d_in[5];
    const float* w4  = (const float*)d_in[6];
    const float* b4  = (const float*)d_in[7];
    const float* sw1 = (const float*)d_in[8];
    const float* sb1 = (const float*)d_in[9];
    const float* sw2 = (const float*)d_in[10];
    const float* sb2 = (const float*)d_in[11];
    float* out = (float*)d_out;

    k1_meanT<<<Nn * Cc, 200>>>(x);
    k2_adj<<<dim3(Nn, 4), 256>>>(A, w1, b1, w2, b2, w4, b4, sw1, sb1, sw2, sb2);
    k3_gemm<<<Nn * Cc, 64>>>(x, out);
}

// round 8
// speedup vs baseline: 1.1325x; 1.1325x over previous
#include <cuda_runtime.h>
#include <math.h>

// Problem constants
#define Nn 128
#define Cc 64
#define Tt 128
#define Vv 25
#define Rr 8
#define Hh 12

// Scratch (device globals; no allocation allowed)
__device__ float g_xm[Nn * Cc * Vv];             // mean over T        (0.8 MB)
__device__ float g_rel[Nn * Rr * Vv * Vv];       // tanh relation      (2.56 MB, L2-resident)
__device__ float g_a[Nn * Vv];                   // SE joint gate      (12.8 KB)

// ================= Kernel 1: xm[n,c,v] = mean_t x[n,c,t,v] =================
// One block per (n,c), 200 threads. Thread j loads float4s at q = j, j+200,
// j+400, j+600 (stride 800 floats == 0 mod 25 -> each component keeps a FIXED
// v). Register accumulation, then a conflict-free stride-25 shared reduction.
__global__ void __launch_bounds__(200) k1_meanT(const float* __restrict__ x) {
    const int b = blockIdx.x;                 // n*C + c
    const int j = threadIdx.x;                // 0..199
    const float4* xp4 = reinterpret_cast<const float4*>(x + (size_t)b * (Tt * Vv));

    float4 a0 = xp4[j];
    float4 a1 = xp4[j + 200];
    float4 a2 = xp4[j + 400];
    float4 a3 = xp4[j + 600];

    __shared__ float red[800];
    red[4 * j + 0] = a0.x + a1.x + a2.x + a3.x;
    red[4 * j + 1] = a0.y + a1.y + a2.y + a3.y;
    red[4 * j + 2] = a0.z + a1.z + a2.z + a3.z;
    red[4 * j + 3] = a0.w + a1.w + a2.w + a3.w;
    __syncthreads();

    if (j < Vv) {
        float tot = 0.f;
        #pragma unroll
        for (int p = 0; p < 32; p++) tot += red[j + Vv * p];
        g_xm[b * Vv + j] = tot * (1.0f / Tt);
    }
}

// ============ Kernel 2 (small): SE gate + relation tensor ============
// One block per n, 256 threads. Writes g_a[n,v] and g_rel[n,r,u,v].
// No Aeff materialization — k3 reconstructs its weight row from rel.
__global__ void k2_rel(const float* __restrict__ w1, const float* __restrict__ b1,
                       const float* __restrict__ w2, const float* __restrict__ b2,
                       const float* __restrict__ sw1, const float* __restrict__ sb1,
                       const float* __restrict__ sw2, const float* __restrict__ sb2) {
    const int n = blockIdx.x;
    const int tid = threadIdx.x;
    const int NT = 256;

    __shared__ float xm_sh[Cc * Vv];
    __shared__ float w1s[Rr * Cc], w2s[Rr * Cc];
    __shared__ float sw1s[Hh * Vv], sw2s[Vv * Hh];
    __shared__ float b1s[Rr], b2s[Rr], sb1s[Hh], sb2s[Vv];
    __shared__ float s_sh[Vv], h_sh[Hh];
    __shared__ float x1_sh[Rr * Vv], x2_sh[Rr * Vv];

    for (int i = tid; i < Cc * Vv; i += NT) xm_sh[i] = g_xm[n * Cc * Vv + i];
    for (int i = tid; i < Rr * Cc; i += NT) { w1s[i] = w1[i]; w2s[i] = w2[i]; }
    for (int i = tid; i < Hh * Vv; i += NT) { sw1s[i] = sw1[i]; sw2s[i] = sw2[i]; }
    if (tid < Rr) { b1s[tid] = b1[tid]; b2s[tid] = b2[tid]; }
    if (tid < Hh) sb1s[tid] = sb1[tid];
    if (tid < Vv) sb2s[tid] = sb2[tid];
    __syncthreads();

    // s[v] = mean_c xm
    if (tid < Vv) {
        float acc = 0.f;
        for (int c = 0; c < Cc; c++) acc += xm_sh[c * Vv + tid];
        s_sh[tid] = acc * (1.0f / Cc);
    }
    __syncthreads();
    if (tid < Hh) {
        float acc = sb1s[tid];
        for (int v = 0; v < Vv; v++) acc += sw1s[tid * Vv + v] * s_sh[v];
        h_sh[tid] = fmaxf(acc, 0.f);
    }
    __syncthreads();
    if (tid < Vv) {
        float acc = sb2s[tid];
        for (int q = 0; q < Hh; q++) acc += sw2s[tid * Hh + q] * h_sh[q];
        g_a[n * Vv + tid] = 1.0f / (1.0f + expf(-acc));
    }

    // x1[r,v], x2[r,v]
    if (tid < Rr * Vv) {
        int r = tid / Vv, v = tid % Vv;
        float acc1 = b1s[r], acc2 = b2s[r];
        for (int c = 0; c < Cc; c++) {
            float xm = xm_sh[c * Vv + v];
            acc1 += w1s[r * Cc + c] * xm;
            acc2 += w2s[r * Cc + c] * xm;
        }
        x1_sh[tid] = acc1;
        x2_sh[tid] = acc2;
    }
    __syncthreads();

    // rel[r,u,v] = tanh(x1[r,u] - x2[r,v]) -> global (2.56 MB total, L2-hot for k3)
    float* relp = g_rel + (size_t)n * (Rr * Vv * Vv);
    for (int i = tid; i < Rr * Vv * Vv; i += NT) {
        int r = i / (Vv * Vv), rem = i % (Vv * Vv);
        int u = rem / Vv, v = rem % Vv;
        relp[i] = tanhf(x1_sh[r * Vv + u] - x2_sh[r * Vv + v]);
    }
}

// ============ Kernel 3 v5: weight reconstruction + GEMM ============
// One block per (n,c), 128 threads, one t-row per thread (proven v2 body).
// Prologue builds Ws[u,v] = (sum_r w4[c,r]*rel[n,r,u,v] + b4[c] + A[u,v]) * a[n,v]
// from L2-resident rel — no 20.5MB Aeff global round-trip.
__global__ void __launch_bounds__(128) k3_gemm(const float* __restrict__ x,
                                               const float* __restrict__ Astat,
                                               const float* __restrict__ w4,
                                               const float* __restrict__ b4,
                                               float* __restrict__ out) {
    __shared__ float xs[Tt * Vv];                      // 12.8 KB; reused as out staging
    __shared__ __align__(16) float Ws[Vv * 28];        // padded rows: 112 B each

    const int b = blockIdx.x;           // n*C + c
    const int n = b >> 6;
    const int c = b & 63;
    const int tid = threadIdx.x;        // 0..127 == t

    // Load x tile (800 float4, coalesced; the only cold-DRAM read)
    const float4* xp4 = reinterpret_cast<const float4*>(x + (size_t)b * (Tt * Vv));
    float4* xs4 = reinterpret_cast<float4*>(xs);
    #pragma unroll
    for (int i = tid; i < (Tt * Vv) / 4; i += 128) xs4[i] = xp4[i];

    // Reconstruct weight matrix from rel (all operands L2-resident)
    {
        float w4c[Rr];
        #pragma unroll
        for (int r = 0; r < Rr; r++) w4c[r] = __ldg(w4 + c * Rr + r);
        const float bias = __ldg(b4 + c);
        const float* relp = g_rel + (size_t)n * (Rr * Vv * Vv);
        const float* ap = g_a + n * Vv;
        for (int e = tid; e < Vv * Vv; e += 128) {
            int u = e / Vv, v = e % Vv;
            float acc = bias + __ldg(Astat + e);
            #pragma unroll
            for (int r = 0; r < Rr; r++) acc += w4c[r] * relp[r * (Vv * Vv) + e];
            Ws[u * 28 + v] = acc * __ldg(ap + v);
        }
        // zero padding columns 25..27
        if (tid < Vv * 3) {
            int u = tid / 3, p = tid % 3;
            Ws[u * 28 + 25 + p] = 0.f;
        }
    }
    __syncthreads();

    // Pull this thread's x row into registers (lane stride 25 ⊥ 32: conflict-free)
    float xv[Vv];
    #pragma unroll
    for (int v = 0; v < Vv; v++) xv[v] = xs[tid * Vv + v];
    __syncthreads();   // xs now free for output staging

    #pragma unroll 1
    for (int u = 0; u < Vv; u++) {
        const float4* wr = reinterpret_cast<const float4*>(Ws + u * 28);
        float4 w0 = wr[0], w1 = wr[1], w2 = wr[2], w3 = wr[3];
        float4 w4r = wr[4], w5 = wr[5], w6 = wr[6];
        float acc0, acc1;
        acc0  = w0.x * xv[0];
        acc1  = w0.y * xv[1];
        acc0 += w0.z * xv[2];
        acc1 += w0.w * xv[3];
        acc0 += w1.x * xv[4];
        acc1 += w1.y * xv[5];
        acc0 += w1.z * xv[6];
        acc1 += w1.w * xv[7];
        acc0 += w2.x * xv[8];
        acc1 += w2.y * xv[9];
        acc0 += w2.z * xv[10];
        acc1 += w2.w * xv[11];
        acc0 += w3.x * xv[12];
        acc1 += w3.y * xv[13];
        acc0 += w3.z * xv[14];
        acc1 += w3.w * xv[15];
        acc0 += w4r.x * xv[16];
        acc1 += w4r.y * xv[17];
        acc0 += w4r.z * xv[18];
        acc1 += w4r.w * xv[19];
        acc0 += w5.x * xv[20];
        acc1 += w5.y * xv[21];
        acc0 += w5.z * xv[22];
        acc1 += w5.w * xv[23];
        acc0 += w6.x * xv[24];
        xs[tid * Vv + u] = acc0 + acc1;
    }
    __syncthreads();

    float4* op4 = reinterpret_cast<float4*>(out + (size_t)b * (Tt * Vv));
    #pragma unroll
    for (int i = tid; i < (Tt * Vv) / 4; i += 128) __stcs(op4 + i, xs4[i]);
}

extern "C" void kernel_launch(void* const* d_in, const int* in_sizes, int n_in,
                              void* d_out, int out_size) {
    const float* x   = (const float*)d_in[0];
    const float* A   = (const float*)d_in[1];
    const float* w1  = (const float*)d_in[2];
    const float* b1  = (const float*)d_in[3];
    const float* w2  = (const float*)d_in[4];
    const float* b2  = (const float*)d_in[5];
    const float* w4  = (const float*)d_in[6];
    const float* b4  = (const float*)d_in[7];
    const float* sw1 = (const float*)d_in[8];
    const float* sb1 = (const float*)d_in[9];
    const float* sw2 = (const float*)d_in[10];
    const float* sb2 = (const float*)d_in[11];
    float* out = (float*)d_out;

    k1_meanT<<<Nn * Cc, 200>>>(x);
    k2_rel<<<Nn, 256>>>(w1, b1, w2, b2, sw1, sb1, sw2, sb2);
    k3_gemm<<<Nn * Cc, 128>>>(x, A, w4, b4, out);
}